// round 1
// baseline (speedup 1.0000x reference)
#include <cuda_runtime.h>
#include <math.h>

// CWT gaus1, scales {1,3,6}, x:(32,4096,64) f32 -> out:(32,3,4096,64) f32.
//
// Folded form: out_a[b,s,c] = sum_m h_a[m] * x[b, s + start_a + m, c]
//   h_a[m] = -sqrt(a)*(f_a[m-1]-f_a[m]),  f_a[i] = int_psi[floor(i/(a*step))]
//   lengths (L+1): a=6 -> 62 taps start -31; a=3 -> 32 taps start -16;
//                  a=1 -> 12 taps start -6.
// Unified window p in [0,61] relative to x[s-31]: scale6 tap m=p (all p),
// scale3 m=p-15 for p in [15,46], scale1 m=p-25 for p in [25,36].
//
// int_psi replicated via Euler-Maclaurin (error ~1e-8 vs numpy cumsum):
//   ip(u) = e^{-u^2} * (1 - h*u + (h^2/12)(4u^2-2)) / (pi/2)^{1/4}

#define S_LEN 4096
#define C_LEN 64
#define TILE_S 64
#define NROWS 125   // TILE_S + 61

__device__ __forceinline__ void ffma2(unsigned long long &d,
                                      unsigned long long a,
                                      unsigned long long b) {
    asm("fma.rn.f32x2 %0, %1, %2, %0;" : "+l"(d) : "l"(a), "l"(b));
}

__device__ __forceinline__ double ipsi_em(long j) {
    const double step = 10.0 / 1023.0;
    double u = (j >= 1023) ? 5.0 : ((double)j * step + (-5.0));
    double e = exp(-u * u);
    double v = e * (1.0 - step * u + (step * step / 12.0) * (4.0 * u * u - 2.0));
    return v / sqrt(sqrt(M_PI / 2.0));   // (pi/2)^(1/4)
}

// f_a[i] as float (numpy casts int_psi[j] to float32); zero outside [0,L)
__device__ __forceinline__ float f_at(int a, int i, int L) {
    if (i < 0 || i >= L) return 0.0f;
    const double step = 10.0 / 1023.0;
    double as_ = (double)a * step;          // matches numpy a*step (f64)
    long j = (long)((double)i / as_);       // matches arange/(a*step) astype(int64)
    return (float)ipsi_em(j);
}

__device__ __forceinline__ float4 to_f4(unsigned long long lo, unsigned long long hi) {
    float4 r;
    r.x = __uint_as_float((unsigned int)(lo));
    r.y = __uint_as_float((unsigned int)(lo >> 32));
    r.z = __uint_as_float((unsigned int)(hi));
    r.w = __uint_as_float((unsigned int)(hi >> 32));
    return r;
}

__global__ void __launch_bounds__(256, 2)
cwt_kernel(const float* __restrict__ x, float* __restrict__ out) {
    __shared__ float xs[NROWS][C_LEN];
    __shared__ unsigned long long g6s[62], g3s[32], g1s[12];

    const int tid  = threadIdx.x;
    const int b    = blockIdx.y;
    const int tile = blockIdx.x;
    const int s0   = tile * TILE_S;

    // ---- fill smem tile (rows s0-31 .. s0+93, zero-padded at edges) ----
    const float4* xg = (const float4*)x + (size_t)b * (S_LEN * (C_LEN / 4));
    const float4 z4 = make_float4(0.f, 0.f, 0.f, 0.f);
    #pragma unroll
    for (int k = 0; k < 8; k++) {
        int f = tid + k * 256;
        if (f < NROWS * 16) {
            int row = f >> 4, q = f & 15;
            int gs = s0 - 31 + row;
            float4 v = (gs >= 0 && gs < S_LEN) ? xg[gs * 16 + q] : z4;
            *(float4*)&xs[row][q * 4] = v;
        }
    }

    // ---- per-block coefficient computation (106 taps) ----
    if (tid < 106) {
        int a, m, L;
        unsigned long long* dst;
        if (tid < 62)       { a = 6; L = 61; m = tid;      dst = &g6s[m]; }
        else if (tid < 94)  { a = 3; L = 31; m = tid - 62; dst = &g3s[m]; }
        else                { a = 1; L = 11; m = tid - 94; dst = &g1s[m]; }
        float h = -(float)sqrt((double)a) * (f_at(a, m - 1, L) - f_at(a, m, L));
        unsigned int bits = __float_as_uint(h);
        *dst = ((unsigned long long)bits << 32) | (unsigned long long)bits;
    }
    __syncthreads();

    // ---- compute: thread = 4 channels x 4 seq positions x 3 scales ----
    const int ch    = tid & 15;     // channel group (4 channels)
    const int tg    = tid >> 4;     // 0..15 seq group
    const int rbase = tg * 4;

    unsigned long long winx[4], winy[4];
    #pragma unroll
    for (int i = 0; i < 4; i++) {
        ulonglong2 v = *(const ulonglong2*)&xs[rbase + i][ch * 4];
        winx[i] = v.x; winy[i] = v.y;
    }

    unsigned long long a6x[4] = {0,0,0,0}, a6y[4] = {0,0,0,0};
    unsigned long long a3x[4] = {0,0,0,0}, a3y[4] = {0,0,0,0};
    unsigned long long a1x[4] = {0,0,0,0}, a1y[4] = {0,0,0,0};

    #pragma unroll
    for (int p = 0; p < 62; p++) {
        unsigned long long c6 = g6s[p];
        #pragma unroll
        for (int t = 0; t < 4; t++) {
            int w = (p + t) & 3;
            ffma2(a6x[t], winx[w], c6);
            ffma2(a6y[t], winy[w], c6);
        }
        if (p >= 15 && p < 47) {
            unsigned long long c3 = g3s[p - 15];
            #pragma unroll
            for (int t = 0; t < 4; t++) {
                int w = (p + t) & 3;
                ffma2(a3x[t], winx[w], c3);
                ffma2(a3y[t], winy[w], c3);
            }
        }
        if (p >= 25 && p < 37) {
            unsigned long long c1 = g1s[p - 25];
            #pragma unroll
            for (int t = 0; t < 4; t++) {
                int w = (p + t) & 3;
                ffma2(a1x[t], winx[w], c1);
                ffma2(a1y[t], winy[w], c1);
            }
        }
        if (p < 61) {   // slide window: load row rbase+p+4
            ulonglong2 v = *(const ulonglong2*)&xs[rbase + p + 4][ch * 4];
            winx[p & 3] = v.x; winy[p & 3] = v.y;
        }
    }

    // ---- store: out[b, scale, s, c], scale order (1,3,6) ----
    float4* og = (float4*)out;
    const size_t ob = (size_t)b * 3 * S_LEN * 16;
    const int srow = s0 + rbase;
    #pragma unroll
    for (int t = 0; t < 4; t++) {
        size_t r = (size_t)(srow + t) * 16 + ch;
        og[ob + 0 * (size_t)S_LEN * 16 + r] = to_f4(a1x[t], a1y[t]);
        og[ob + 1 * (size_t)S_LEN * 16 + r] = to_f4(a3x[t], a3y[t]);
        og[ob + 2 * (size_t)S_LEN * 16 + r] = to_f4(a6x[t], a6y[t]);
    }
}

extern "C" void kernel_launch(void* const* d_in, const int* in_sizes, int n_in,
                              void* d_out, int out_size) {
    const float* x = (const float*)d_in[0];
    float* out = (float*)d_out;
    dim3 grid(S_LEN / TILE_S, 32);   // (64 seq tiles, 32 batches)
    cwt_kernel<<<grid, 256>>>(x, out);
}